// round 2
// baseline (speedup 1.0000x reference)
#include <cuda_runtime.h>

// Problem dims
#define D   128
#define P0  64
#define C1  512
#define C2  2048

// Output layout (floats), concatenated in reference tuple order
#define O0  0          // root_mu_min   (64,128)
#define O1  8192       // root_mu_max
#define O2  16384      // beta_min
#define O3  24576      // beta_max
#define O4  32768      // mu_min level1 (512,128)
#define O5  98304      // mu_max level1
#define O6  163840     // b_min level1
#define O7  229376     // b_max level1
#define O8  294912     // mu_min level2 (2048,128)
#define O9  557056     // mu_max level2
#define O10 819200     // b_min level2
#define O11 1081344    // b_max level2

#define EPSF   1e-10f
#define L2EPS  -33.21928095f           // log2(1e-10)
#define LOG2E  1.4426950408889634f
#define LN2    0.6931471805599453f

// scratch: hard gumbel gates (exactly 0.0f / 1.0f)
__device__ float g_w0[C1 * P0];
__device__ float g_w1[C2 * C1];

__device__ __forceinline__ float ex2f(float x) {
    float y;
    asm("ex2.approx.ftz.f32 %0, %1;" : "=f"(y) : "f"(x));
    return y;
}

// ---------------- level 0: copy mu, beta = sigmoid(raw) + 1e-6 ----------------
__global__ void k_level0(const float* __restrict__ mu_min,
                         const float* __restrict__ mu_max,
                         const float* __restrict__ bmin_raw,
                         const float* __restrict__ bmax_raw,
                         float* __restrict__ out) {
    int i = blockIdx.x * blockDim.x + threadIdx.x;
    if (i < P0 * D) {
        out[O0 + i] = mu_min[i];
        out[O1 + i] = mu_max[i];
        out[O2 + i] = 1.0f / (1.0f + expf(-bmin_raw[i])) + 1e-6f;
        out[O3 + i] = 1.0f / (1.0f + expf(-bmax_raw[i])) + 1e-6f;
    }
}

// ---------------- gumbel-sigmoid hard gates (forward value is binary) ----------
__global__ void k_gumbel(const float* __restrict__ l0, const float* __restrict__ u0,
                         const float* __restrict__ l1, const float* __restrict__ u1) {
    int i = blockIdx.x * blockDim.x + threadIdx.x;
    const int n0 = C1 * P0;
    if (i < n0) {
        float g  = -logf(-logf(u0[i] + EPSF) + EPSF);
        float ys = 1.0f / (1.0f + expf(-(l0[i] + g) * 2.0f));  // TEMP = 0.5
        g_w0[i] = (ys > 0.5f) ? 1.0f : 0.0f;
    } else {
        int j = i - n0;
        if (j < C2 * C1) {
            float g  = -logf(-logf(u1[j] + EPSF) + EPSF);
            float ys = 1.0f / (1.0f + expf(-(l1[j] + g) * 2.0f));
            g_w1[j] = (ys > 0.5f) ? 1.0f : 0.0f;
        }
    }
}

// ---------------- level 1 intersection: C=512, P=64 ----------------
// One block per child c, one thread per dim d.
__global__ void k_level1(float* __restrict__ out) {
    __shared__ float sh_w[P0];
    const int c = blockIdx.x;
    const int d = threadIdx.x;
    if (d < P0) sh_w[d] = g_w0[c * P0 + d];
    __syncthreads();

    const float* __restrict__ mu_min = out + O0;
    const float* __restrict__ mu_max = out + O1;
    const float* __restrict__ be_min = out + O2;
    const float* __restrict__ be_max = out + O3;

    float bA = 0.f, bB = 0.f, ws = 0.f;
    float mx = -1e30f, mn = 1e30f;
#pragma unroll 4
    for (int p = 0; p < P0; p++) {
        float w = sh_w[p];
        ws += w;
        bA = fmaf(w, be_min[p * D + d], bA);
        bB = fmaf(w, be_max[p * D + d], bB);
        mx = fmaxf(mx, mu_min[p * D + d]);
        mn = fminf(mn, mu_max[p * D + d]);
    }
    float wsE  = ws + EPSF;
    float bmin = bA / wsE, bmax = bB / wsE;
    out[O6 + c * D + d] = bmin;
    out[O7 + c * D + d] = bmax;

    float ibn = LOG2E / bmin, ibx = LOG2E / bmax;
    float Sn = 0.f, Sx = 0.f;
#pragma unroll 4
    for (int p = 0; p < P0; p++) {
        float lw2 = (1.0f - sh_w[p]) * L2EPS;   // 0 if selected, log2(eps) otherwise
        Sn += ex2f(fmaf(mu_min[p * D + d] - mx, ibn, lw2));
        Sx += ex2f(fmaf(mn - mu_max[p * D + d], ibx, lw2));
    }
    out[O4 + c * D + d] =  bmin * (logf(Sn) + mx * (ibn * LN2));
    out[O5 + c * D + d] = -bmax * (logf(Sx) - mn * (ibx * LN2));
}

// ---------------- level 2 intersection: C=2048, P=512, NC children/block ------
#define NC 8
__global__ void __launch_bounds__(D) k_level2(float* __restrict__ out) {
    __shared__ float sh[NC][C1];   // 16 KB: gate row per child, later log2-weights
    const int c0 = blockIdx.x * NC;
    const int d  = threadIdx.x;

    for (int idx = d; idx < NC * C1; idx += D)
        sh[idx >> 9][idx & (C1 - 1)] = g_w1[c0 * C1 + idx];
    __syncthreads();

    const float* __restrict__ mu_min = out + O4;
    const float* __restrict__ mu_max = out + O5;
    const float* __restrict__ be_min = out + O6;
    const float* __restrict__ be_max = out + O7;

    // pass 1: weighted beta sums, wsum, and c-independent column max/min of mu
    float bA[NC], bB[NC], ws[NC];
#pragma unroll
    for (int i = 0; i < NC; i++) { bA[i] = 0.f; bB[i] = 0.f; ws[i] = 0.f; }
    float mx = -1e30f, mn = 1e30f;
    for (int p = 0; p < C1; p++) {
        float b0 = be_min[p * D + d];
        float b1 = be_max[p * D + d];
        mx = fmaxf(mx, mu_min[p * D + d]);
        mn = fminf(mn, mu_max[p * D + d]);
#pragma unroll
        for (int i = 0; i < NC; i++) {
            float w = sh[i][p];
            ws[i] += w;
            bA[i] = fmaf(w, b0, bA[i]);
            bB[i] = fmaf(w, b1, bB[i]);
        }
    }
    __syncthreads();
    // convert gates to log2-weights in place
    for (int idx = d; idx < NC * C1; idx += D) {
        float w = sh[idx >> 9][idx & (C1 - 1)];
        sh[idx >> 9][idx & (C1 - 1)] = (1.0f - w) * L2EPS;
    }
    __syncthreads();

    float bmin[NC], bmax[NC], ibn[NC], ibx[NC], Sn[NC], Sx[NC];
#pragma unroll
    for (int i = 0; i < NC; i++) {
        float wsE = ws[i] + EPSF;
        bmin[i] = bA[i] / wsE;
        bmax[i] = bB[i] / wsE;
        out[O10 + (c0 + i) * D + d] = bmin[i];
        out[O11 + (c0 + i) * D + d] = bmax[i];
        ibn[i] = LOG2E / bmin[i];
        ibx[i] = LOG2E / bmax[i];
        Sn[i] = 0.f;
        Sx[i] = 0.f;
    }

    // pass 2: single-pass LSE with hoisted upper-bound max:
    //   arg - Mhat = ib2 * (mu - colmax) + log2(w+eps)
    for (int p = 0; p < C1; p++) {
        float mm = mu_min[p * D + d] - mx;   // <= 0
        float pm = mn - mu_max[p * D + d];   // <= 0
#pragma unroll
        for (int i = 0; i < NC; i++) {
            float lw2 = sh[i][p];
            Sn[i] += ex2f(fmaf(mm, ibn[i], lw2));
            Sx[i] += ex2f(fmaf(pm, ibx[i], lw2));
        }
    }

#pragma unroll
    for (int i = 0; i < NC; i++) {
        out[O8 + (c0 + i) * D + d] =  bmin[i] * (logf(Sn[i]) + mx * (ibn[i] * LN2));
        out[O9 + (c0 + i) * D + d] = -bmax[i] * (logf(Sx[i]) - mn * (ibx[i] * LN2));
    }
}

extern "C" void kernel_launch(void* const* d_in, const int* in_sizes, int n_in,
                              void* d_out, int out_size) {
    const float* root_mu_min   = (const float*)d_in[0];
    const float* root_mu_max   = (const float*)d_in[1];
    const float* root_bmin_raw = (const float*)d_in[2];
    const float* root_bmax_raw = (const float*)d_in[3];
    const float* adj_logits0   = (const float*)d_in[4];
    const float* adj_logits1   = (const float*)d_in[5];
    const float* u0            = (const float*)d_in[6];
    const float* u1            = (const float*)d_in[7];
    float* out = (float*)d_out;

    k_level0<<<(P0 * D + 255) / 256, 256>>>(root_mu_min, root_mu_max,
                                            root_bmin_raw, root_bmax_raw, out);
    int ngum = C1 * P0 + C2 * C1;
    k_gumbel<<<(ngum + 255) / 256, 256>>>(adj_logits0, u0, adj_logits1, u1);
    k_level1<<<C1, D>>>(out);
    k_level2<<<C2 / NC, D>>>(out);
}

// round 4
// speedup vs baseline: 1.5423x; 1.5423x over previous
#include <cuda_runtime.h>

// Problem dims
#define D   128
#define P0  64
#define C1  512
#define C2  2048

// Output layout (floats), concatenated in reference tuple order
#define O0  0          // root_mu_min   (64,128)
#define O1  8192       // root_mu_max
#define O2  16384      // beta_min
#define O3  24576      // beta_max
#define O4  32768      // mu_min level1 (512,128)
#define O5  98304      // mu_max level1
#define O6  163840     // b_min level1
#define O7  229376     // b_max level1
#define O8  294912     // mu_min level2 (2048,128)
#define O9  557056     // mu_max level2
#define O10 819200     // b_min level2
#define O11 1081344    // b_max level2

#define EPSF   1e-10f
#define L2EPS  -33.21928095f           // log2(1e-10)
#define LOG2E  1.4426950408889634f
#define LN2    0.6931471805599453f

// scratch: hard gumbel gates (exactly 0.0f / 1.0f)
__device__ float g_w0[C1 * P0];
__device__ float g_w1[C2 * C1];
// column max/min of level-1 mu (block-independent)
__device__ float g_mx[D];
__device__ float g_mn[D];

__device__ __forceinline__ float ex2f(float x) {
    float y;
    asm("ex2.approx.ftz.f32 %0, %1;" : "=f"(y) : "f"(x));
    return y;
}

// ---------------- level 0: copy mu, beta = sigmoid(raw) + 1e-6 ----------------
__global__ void k_level0(const float* __restrict__ mu_min,
                         const float* __restrict__ mu_max,
                         const float* __restrict__ bmin_raw,
                         const float* __restrict__ bmax_raw,
                         float* __restrict__ out) {
    int i = blockIdx.x * blockDim.x + threadIdx.x;
    if (i < P0 * D) {
        out[O0 + i] = mu_min[i];
        out[O1 + i] = mu_max[i];
        out[O2 + i] = 1.0f / (1.0f + expf(-bmin_raw[i])) + 1e-6f;
        out[O3 + i] = 1.0f / (1.0f + expf(-bmax_raw[i])) + 1e-6f;
    }
}

// ---------------- gumbel-sigmoid hard gates (forward value is binary) ----------
__global__ void k_gumbel(const float* __restrict__ l0, const float* __restrict__ u0,
                         const float* __restrict__ l1, const float* __restrict__ u1) {
    int i = blockIdx.x * blockDim.x + threadIdx.x;
    const int n0 = C1 * P0;
    if (i < n0) {
        float g  = -logf(-logf(u0[i] + EPSF) + EPSF);
        float ys = 1.0f / (1.0f + expf(-(l0[i] + g) * 2.0f));  // TEMP = 0.5
        g_w0[i] = (ys > 0.5f) ? 1.0f : 0.0f;
    } else {
        int j = i - n0;
        if (j < C2 * C1) {
            float g  = -logf(-logf(u1[j] + EPSF) + EPSF);
            float ys = 1.0f / (1.0f + expf(-(l1[j] + g) * 2.0f));
            g_w1[j] = (ys > 0.5f) ? 1.0f : 0.0f;
        }
    }
}

// ---------------- level 1 intersection: C=512, P=64 ----------------
// One block per child c, one thread per dim d. (dense, small: ~4% of work)
__global__ void k_level1(float* __restrict__ out) {
    __shared__ float sh_w[P0];
    const int c = blockIdx.x;
    const int d = threadIdx.x;
    if (d < P0) sh_w[d] = g_w0[c * P0 + d];
    __syncthreads();

    const float* __restrict__ mu_min = out + O0;
    const float* __restrict__ mu_max = out + O1;
    const float* __restrict__ be_min = out + O2;
    const float* __restrict__ be_max = out + O3;

    float bA = 0.f, bB = 0.f, ws = 0.f;
    float mx = -1e30f, mn = 1e30f;
#pragma unroll 8
    for (int p = 0; p < P0; p++) {
        float w = sh_w[p];
        ws += w;
        bA = fmaf(w, be_min[p * D + d], bA);
        bB = fmaf(w, be_max[p * D + d], bB);
        mx = fmaxf(mx, mu_min[p * D + d]);
        mn = fminf(mn, mu_max[p * D + d]);
    }
    float wsE  = ws + EPSF;
    float bmin = bA / wsE, bmax = bB / wsE;
    out[O6 + c * D + d] = bmin;
    out[O7 + c * D + d] = bmax;

    float ibn = LOG2E / bmin, ibx = LOG2E / bmax;
    float Sn = 0.f, Sx = 0.f;
#pragma unroll 8
    for (int p = 0; p < P0; p++) {
        float lw2 = (1.0f - sh_w[p]) * L2EPS;   // 0 if selected, log2(eps) otherwise
        Sn += ex2f(fmaf(mu_min[p * D + d] - mx, ibn, lw2));
        Sx += ex2f(fmaf(mn - mu_max[p * D + d], ibx, lw2));
    }
    out[O4 + c * D + d] = fmaf(bmin, logf(Sn), mx);
    out[O5 + c * D + d] = fmaf(-bmax, logf(Sx), mn);
}

// ---------------- column max/min of level-1 mu over all 512 parents ------------
// One block of 512 threads: thread (d, q) covers rows [q*128, q*128+128).
__global__ void __launch_bounds__(512) k_colmax(const float* __restrict__ out) {
    __shared__ float sA[512], sB[512];
    const int t = threadIdx.x;
    const int d = t & (D - 1);
    const int q = t >> 7;
    const float* __restrict__ mu_min = out + O4;
    const float* __restrict__ mu_max = out + O5;
    float mx = -1e30f, mn = 1e30f;
#pragma unroll 8
    for (int r = 0; r < 128; r++) {
        int p = q * 128 + r;
        mx = fmaxf(mx, mu_min[p * D + d]);
        mn = fminf(mn, mu_max[p * D + d]);
    }
    sA[t] = mx; sB[t] = mn;
    __syncthreads();
    if (q == 0) {
#pragma unroll
        for (int k = 1; k < 4; k++) {
            mx = fmaxf(mx, sA[d + k * 128]);
            mn = fminf(mn, sB[d + k * 128]);
        }
        g_mx[d] = mx;
        g_mn[d] = mn;
    }
}

// ---------------- level 2 intersection: C=2048, P=512, NC children/block ------
#define NC 8
#define U  8

// load 8 u16 indices (one LDS.128) and gather the two mu rows for each
__device__ __forceinline__ void ld8(const unsigned short* __restrict__ lst,
                                    const float* __restrict__ A,
                                    const float* __restrict__ B,
                                    int d, float* m, float* q) {
    uint4 iv = *reinterpret_cast<const uint4*>(lst);
    unsigned idx[U] = { iv.x & 0xffffu, iv.x >> 16, iv.y & 0xffffu, iv.y >> 16,
                        iv.z & 0xffffu, iv.z >> 16, iv.w & 0xffffu, iv.w >> 16 };
#pragma unroll
    for (int u = 0; u < U; u++) {
        m[u] = A[idx[u] * D + d];
        q[u] = B[idx[u] * D + d];
    }
}

__global__ void __launch_bounds__(D) k_level2(float* __restrict__ out) {
    __shared__ float s_w[C1][NC];                        // transposed gates, 16KB
    __shared__ __align__(16) unsigned short s_idx[NC][C1]; // selected-parent lists, 8KB
    __shared__ int s_cnt[NC];
    const int c0 = blockIdx.x * NC;
    const int d  = threadIdx.x;
    const int warp = d >> 5, lane = d & 31;

    // stage gates transposed: s_w[p][i]
    for (int idx = d; idx < NC * C1; idx += D) {
        int i = idx & (NC - 1);
        int p = idx >> 3;
        s_w[p][i] = g_w1[(c0 + i) * C1 + p];
    }
    __syncthreads();

    // ballot-compact selected parents: warp w handles children {2w, 2w+1}
#pragma unroll
    for (int ii = 0; ii < 2; ii++) {
        int i = warp * 2 + ii;
        int base = 0;
        for (int chunk = 0; chunk < C1; chunk += 32) {
            float w = s_w[chunk + lane][i];
            unsigned m = __ballot_sync(0xffffffffu, w > 0.5f);
            if (w > 0.5f) {
                int pre = __popc(m & ((1u << lane) - 1u));
                s_idx[i][base + pre] = (unsigned short)(chunk + lane);
            }
            base += __popc(m);
        }
        if (lane == 0) s_cnt[i] = base;
    }

    const float* __restrict__ mu_min = out + O4;
    const float* __restrict__ mu_max = out + O5;
    const float* __restrict__ be_min = out + O6;
    const float* __restrict__ be_max = out + O7;
    const float mx = g_mx[d], mn = g_mn[d];

    // pass 1: dense weighted beta sums, register double-buffered prefetch
    float bA[NC], bB[NC];
#pragma unroll
    for (int i = 0; i < NC; i++) { bA[i] = 0.f; bB[i] = 0.f; }
    {
        float b0n[U], b1n[U];
#pragma unroll
        for (int u = 0; u < U; u++) {
            b0n[u] = be_min[u * D + d];
            b1n[u] = be_max[u * D + d];
        }
        for (int p0 = 0; p0 < C1; p0 += U) {
            float b0c[U], b1c[U];
#pragma unroll
            for (int u = 0; u < U; u++) { b0c[u] = b0n[u]; b1c[u] = b1n[u]; }
            if (p0 + U < C1) {
#pragma unroll
                for (int u = 0; u < U; u++) {
                    b0n[u] = be_min[(p0 + U + u) * D + d];
                    b1n[u] = be_max[(p0 + U + u) * D + d];
                }
            }
#pragma unroll
            for (int u = 0; u < U; u++) {
                const float4 wa = *reinterpret_cast<const float4*>(&s_w[p0 + u][0]);
                const float4 wb = *reinterpret_cast<const float4*>(&s_w[p0 + u][4]);
                bA[0] = fmaf(wa.x, b0c[u], bA[0]);
                bA[1] = fmaf(wa.y, b0c[u], bA[1]);
                bA[2] = fmaf(wa.z, b0c[u], bA[2]);
                bA[3] = fmaf(wa.w, b0c[u], bA[3]);
                bA[4] = fmaf(wb.x, b0c[u], bA[4]);
                bA[5] = fmaf(wb.y, b0c[u], bA[5]);
                bA[6] = fmaf(wb.z, b0c[u], bA[6]);
                bA[7] = fmaf(wb.w, b0c[u], bA[7]);
                bB[0] = fmaf(wa.x, b1c[u], bB[0]);
                bB[1] = fmaf(wa.y, b1c[u], bB[1]);
                bB[2] = fmaf(wa.z, b1c[u], bB[2]);
                bB[3] = fmaf(wa.w, b1c[u], bB[3]);
                bB[4] = fmaf(wb.x, b1c[u], bB[4]);
                bB[5] = fmaf(wb.y, b1c[u], bB[5]);
                bB[6] = fmaf(wb.z, b1c[u], bB[6]);
                bB[7] = fmaf(wb.w, b1c[u], bB[7]);
            }
        }
    }
    __syncthreads();   // s_idx/s_cnt from all warps visible

    // pass 2: per child, LSE over SELECTED parents only (w=1 -> log-weight 0;
    // w=0 terms are <= 1e-10 of a sum that is ~O(1): dropped)
    for (int i = 0; i < NC; i++) {
        const int cnt = s_cnt[i];
        const float wsE  = (float)cnt + EPSF;
        const float bmin = bA[i] / wsE;
        const float bmax = bB[i] / wsE;
        out[O10 + (c0 + i) * D + d] = bmin;
        out[O11 + (c0 + i) * D + d] = bmax;
        const float ibn = LOG2E / bmin, ibx = LOG2E / bmax;
        const float cmin = -mx * ibn,  cmax = mn * ibx;
        float Sn = 0.f, Sx = 0.f;
        const unsigned short* lst = s_idx[i];
        const int cnt8 = cnt & ~(U - 1);

        float mmb[U], pmb[U];
        if (cnt8 > 0) ld8(lst, mu_min, mu_max, d, mmb, pmb);
        for (int j = 0; j < cnt8; j += U) {
            float mmc[U], pmc[U];
#pragma unroll
            for (int u = 0; u < U; u++) { mmc[u] = mmb[u]; pmc[u] = pmb[u]; }
            if (j + U < cnt8) ld8(lst + j + U, mu_min, mu_max, d, mmb, pmb);
#pragma unroll
            for (int u = 0; u < U; u++) {
                Sn += ex2f(fmaf(mmc[u],  ibn, cmin));
                Sx += ex2f(fmaf(pmc[u], -ibx, cmax));
            }
        }
        for (int j = cnt8; j < cnt; j++) {
            int p = lst[j];
            Sn += ex2f(fmaf(mu_min[p * D + d],  ibn, cmin));
            Sx += ex2f(fmaf(mu_max[p * D + d], -ibx, cmax));
        }
        out[O8 + (c0 + i) * D + d] = fmaf(bmin, logf(Sn), mx);
        out[O9 + (c0 + i) * D + d] = fmaf(-bmax, logf(Sx), mn);
    }
}

extern "C" void kernel_launch(void* const* d_in, const int* in_sizes, int n_in,
                              void* d_out, int out_size) {
    const float* root_mu_min   = (const float*)d_in[0];
    const float* root_mu_max   = (const float*)d_in[1];
    const float* root_bmin_raw = (const float*)d_in[2];
    const float* root_bmax_raw = (const float*)d_in[3];
    const float* adj_logits0   = (const float*)d_in[4];
    const float* adj_logits1   = (const float*)d_in[5];
    const float* u0            = (const float*)d_in[6];
    const float* u1            = (const float*)d_in[7];
    float* out = (float*)d_out;

    k_level0<<<(P0 * D + 255) / 256, 256>>>(root_mu_min, root_mu_max,
                                            root_bmin_raw, root_bmax_raw, out);
    int ngum = C1 * P0 + C2 * C1;
    k_gumbel<<<(ngum + 255) / 256, 256>>>(adj_logits0, u0, adj_logits1, u1);
    k_level1<<<C1, D>>>(out);
    k_colmax<<<1, 512>>>(out);
    k_level2<<<C2 / NC, D>>>(out);
}